// round 7
// baseline (speedup 1.0000x reference)
#include <cuda_runtime.h>
#include <cuda_bf16.h>
#include <cstdint>

#define BATCH 8192
#define DIN   1024
#define DSAE  16384
#define TOPK  32
#define CAP   768
#define NB_MAX 64
#define BAND  2.0e-2f
#define FB_MAX 128

// ---------------- scratch ----------------
__device__ int    g_tk_idx[BATCH * TOPK];
__device__ float  g_tk_val[BATCH * TOPK];
__device__ double g_loss_sum;
__device__ float  g_l0_sum;
__device__ float  g_T0[BATCH];
__device__ int    g_cnt[BATCH];
__device__ int    g_flag[BATCH];
__device__ int    g_fbn;
__device__ __align__(16)   uint2 g_cand[(size_t)BATCH * CAP];
__device__ __align__(16)   double g_fbv[(size_t)FB_MAX * DSAE];
__device__ __align__(1024) __nv_bfloat16 g_Xh[BATCH * DIN];
__device__ __align__(1024) __nv_bfloat16 g_Wh[(size_t)DSAE * DIN];
__device__ __align__(1024) float         g_WT[(size_t)DSAE * DIN];

__global__ void init_kernel() {
    const int i = blockIdx.x * blockDim.x + threadIdx.x;
    if (i < BATCH) { g_cnt[i] = 0; g_flag[i] = 0; }
    if (i == 0) { g_loss_sum = 0.0; g_l0_sum = 0.0f; g_fbn = 0; }
}

// ---------------- prep: bf16 x + per-row candidate threshold ----------------
__global__ __launch_bounds__(256)
void splitx_kernel(const float* __restrict__ x)
{
    const int row  = blockIdx.x * 8 + (threadIdx.x >> 5);
    const int lane = threadIdx.x & 31;
    const float* xr = x + (size_t)row * DIN;
    __nv_bfloat16* dr = g_Xh + (size_t)row * DIN;
    float ss = 0.f;
    #pragma unroll
    for (int i = 0; i < 8; i++) {
        const int k = lane * 4 + i * 128;
        const float4 v = *(const float4*)(xr + k);
        ss += v.x * v.x + v.y * v.y + v.z * v.z + v.w * v.w;
        dr[k + 0] = __float2bfloat16_rn(v.x);
        dr[k + 1] = __float2bfloat16_rn(v.y);
        dr[k + 2] = __float2bfloat16_rn(v.z);
        dr[k + 3] = __float2bfloat16_rn(v.w);
    }
    #pragma unroll
    for (int o = 16; o > 0; o >>= 1) ss += __shfl_xor_sync(0xFFFFFFFFu, ss, o);
    if (lane == 0) g_T0[row] = 2.40f * 0.04419417f * sqrtf(ss);
}

// ---------------- prep: transpose W_enc -> fp32 W^T + bf16 W^T ----------------
__global__ __launch_bounds__(256)
void splitw_kernel(const float* __restrict__ W)
{
    __shared__ float t[32][33];
    const int n0 = blockIdx.x * 32, k0 = blockIdx.y * 32;
    const int tx = threadIdx.x, ty = threadIdx.y;  // 32 x 8
    #pragma unroll
    for (int i = 0; i < 32; i += 8)
        t[ty + i][tx] = W[(size_t)(k0 + ty + i) * DSAE + n0 + tx];
    __syncthreads();
    #pragma unroll
    for (int i = 0; i < 32; i += 8) {
        const float v = t[tx][ty + i];
        const size_t o = (size_t)(n0 + ty + i) * DIN + k0 + tx;
        g_Wh[o] = __float2bfloat16_rn(v);
        g_WT[o] = v;
    }
}

// ---------------- helpers ----------------
__device__ __forceinline__ uint32_t smem_u32(const void* p) {
    uint32_t a;
    asm("{ .reg .u64 t; cvta.to.shared.u64 t, %1; cvt.u32.u64 %0, t; }" : "=r"(a) : "l"(p));
    return a;
}
#define SWZ(off) ((off) ^ (((off) >> 3) & 0x70))

__device__ __forceinline__ void ldsm4(uint32_t* r, uint32_t addr) {
    asm volatile("ldmatrix.sync.aligned.m8n8.x4.shared.b16 {%0,%1,%2,%3}, [%4];"
        : "=r"(r[0]), "=r"(r[1]), "=r"(r[2]), "=r"(r[3]) : "r"(addr));
}
__device__ __forceinline__ void mma_bf16(float* d, const uint32_t* a, const uint32_t* b) {
    asm volatile(
        "mma.sync.aligned.m16n8k16.row.col.f32.bf16.bf16.f32 "
        "{%0,%1,%2,%3}, {%4,%5,%6,%7}, {%8,%9}, {%0,%1,%2,%3};"
        : "+f"(d[0]), "+f"(d[1]), "+f"(d[2]), "+f"(d[3])
        : "r"(a[0]), "r"(a[1]), "r"(a[2]), "r"(a[3]), "r"(b[0]), "r"(b[1]));
}

// smem: 3 buffers x 48KB (A 16K | B 32K), then bias 1KB, T0 512B
#define SBUF     49152
#define OFF_A    0
#define OFF_B    16384
#define OFF_BIAS 147456
#define OFF_T0   148480
#define SM_TOTAL 148992

// ---------------- encoder GEMM: CTA 128x256, warp tile 64x64, 3-stage pipeline ----------------
__global__ __launch_bounds__(256, 1)
void gemm_mma_kernel(const float* __restrict__ bias, float* __restrict__ H)
{
    extern __shared__ char smem[];
    const uint32_t sb = smem_u32(smem);
    const int tid  = threadIdx.x;
    const int wid  = tid >> 5, lane = tid & 31;
    const int m0   = blockIdx.y * 128;
    const int n0   = blockIdx.x * 256;
    const int m_off = (wid & 1) * 64;
    const int n_off = (wid >> 1) * 64;

    *(float*)(smem + OFF_BIAS + tid * 4) = bias[n0 + tid];
    if (tid < 128) *(float*)(smem + OFF_T0 + tid * 4) = g_T0[m0 + tid];

    float acc[4][8][4] = {};

#define ISSUE_STAGE(s) do {                                                          \
    const int k0_ = (s) * 64;                                                        \
    const uint32_t base_ = sb + ((s) % 3) * SBUF;                                    \
    _Pragma("unroll")                                                                \
    for (int i = 0; i < 4; i++) {                                                    \
        const int c = tid + i * 256;                                                 \
        const int row = c >> 3, c16 = c & 7;                                         \
        const uint32_t off = SWZ((uint32_t)(row * 128 + c16 * 16));                  \
        const size_t gA = (size_t)(m0 + row) * DIN + k0_ + c16 * 8;                  \
        asm volatile("cp.async.cg.shared.global [%0], [%1], 16;"                     \
                     :: "r"(base_ + OFF_A + off), "l"(g_Xh + gA) : "memory");        \
    }                                                                                \
    _Pragma("unroll")                                                                \
    for (int i = 0; i < 8; i++) {                                                    \
        const int c = tid + i * 256;                                                 \
        const int row = c >> 3, c16 = c & 7;                                         \
        const uint32_t off = SWZ((uint32_t)(row * 128 + c16 * 16));                  \
        const size_t gB = (size_t)(n0 + row) * DIN + k0_ + c16 * 8;                  \
        asm volatile("cp.async.cg.shared.global [%0], [%1], 16;"                     \
                     :: "r"(base_ + OFF_B + off), "l"(g_Wh + gB) : "memory");        \
    }                                                                                \
    asm volatile("cp.async.commit_group;" ::: "memory");                             \
} while (0)

    ISSUE_STAGE(0);
    ISSUE_STAGE(1);

    const int NST = DIN / 64;  // 16
    for (int s = 0; s < NST; s++) {
        if (s + 2 < NST) {
            ISSUE_STAGE(s + 2);
            asm volatile("cp.async.wait_group 2;" ::: "memory");
        } else if (s + 1 < NST) {
            asm volatile("cp.async.wait_group 1;" ::: "memory");
        } else {
            asm volatile("cp.async.wait_group 0;" ::: "memory");
        }
        __syncthreads();

        const uint32_t base = sb + (s % 3) * SBUF;
        #pragma unroll
        for (int ks = 0; ks < 4; ks++) {
            const int kb = ks * 16;
            uint32_t ah[4][4];
            #pragma unroll
            for (int fm = 0; fm < 4; fm++) {
                const int row = m_off + fm * 16 + (lane & 15);
                const int col = kb + (lane >> 4) * 8;
                const uint32_t off = SWZ((uint32_t)(row * 128 + col * 2));
                ldsm4(ah[fm], base + OFF_A + off);
            }
            uint32_t bh[8][2];
            #pragma unroll
            for (int p = 0; p < 4; p++) {
                const int nrow = n_off + p * 16 + (lane & 7) + ((lane >> 4) & 1) * 8;
                const int kcol = kb + ((lane >> 3) & 1) * 8;
                const uint32_t off = SWZ((uint32_t)(nrow * 128 + kcol * 2));
                uint32_t t[4];
                ldsm4(t, base + OFF_B + off);
                bh[2 * p][0] = t[0]; bh[2 * p][1] = t[1];
                bh[2 * p + 1][0] = t[2]; bh[2 * p + 1][1] = t[3];
            }
            #pragma unroll
            for (int fm = 0; fm < 4; fm++)
                #pragma unroll
                for (int fn = 0; fn < 8; fn++)
                    mma_bf16(acc[fm][fn], ah[fm], bh[fn]);
        }
        __syncthreads();
    }
#undef ISSUE_STAGE

    // epilogue: zero-fill h_sparse tile; candidates (v > T0[row]) -> global list
    const float* bs = (const float*)(smem + OFF_BIAS);
    const float* t0 = (const float*)(smem + OFF_T0);
    #pragma unroll
    for (int fm = 0; fm < 4; fm++) {
        #pragma unroll
        for (int fn = 0; fn < 8; fn++) {
            const int nc = n_off + fn * 8 + (lane & 3) * 2;
            const float b0 = bs[nc], b1 = bs[nc + 1];
            #pragma unroll
            for (int half = 0; half < 2; half++) {
                const int lr = m_off + fm * 16 + (lane >> 2) + half * 8;
                const int m = m0 + lr;
                const float v0 = acc[fm][fn][half * 2 + 0] + b0;
                const float v1 = acc[fm][fn][half * 2 + 1] + b1;
                *(float2*)(H + (size_t)m * DSAE + n0 + nc) = make_float2(0.f, 0.f);
                const float th = t0[lr];
                if (v0 > th) {
                    const int p = atomicAdd(&g_cnt[m], 1);
                    if (p < CAP) g_cand[(size_t)m * CAP + p] =
                        make_uint2(__float_as_uint(v0), (unsigned)(n0 + nc));
                }
                if (v1 > th) {
                    const int p = atomicAdd(&g_cnt[m], 1);
                    if (p < CAP) g_cand[(size_t)m * CAP + p] =
                        make_uint2(__float_as_uint(v1), (unsigned)(n0 + nc + 1));
                }
            }
        }
    }
}

// ---------------- fused select + valuefix + decode + loss (per row) ----------------
__global__ __launch_bounds__(128)
void select_decode_kernel(const float* __restrict__ x, const float* __restrict__ benc,
                          const float* __restrict__ Wdec, const float* __restrict__ bdec,
                          float* __restrict__ H, float* __restrict__ xhat)
{
    __shared__ float sval[CAP];
    __shared__ int   sidx[CAP];
    __shared__ unsigned char ssel[CAP];
    __shared__ int   stop[TOPK];
    __shared__ int   s_band[NB_MAX];
    __shared__ double s_exact[NB_MAX];
    __shared__ double dred[128];
    __shared__ int   s_nb, s_nsb, s_l0;
    __shared__ int   s_final[TOPK];
    __shared__ int   s_fidx[TOPK];
    __shared__ float s_fval[TOPK];
    __shared__ float red[128];

    const int row = blockIdx.x;
    const int tid = threadIdx.x;
    const int n = g_cnt[row];
    if (n < TOPK || n > CAP) { if (tid == 0) g_flag[row] = 1; return; }

    for (int i = tid; i < n; i += 128) {
        const uint2 c = g_cand[(size_t)row * CAP + i];
        sval[i] = __uint_as_float(c.x);
        sidx[i] = (int)c.y;
    }
    if (tid == 0) { s_nb = 0; s_nsb = 0; s_l0 = 0; }
    __syncthreads();

    // exact rank by (value desc, idx asc)
    for (int i = tid; i < n; i += 128) {
        const float vi = sval[i]; const int ii = sidx[i];
        int r = 0;
        for (int j = 0; j < n; j++) {
            const float vj = sval[j];
            r += (vj > vi) || (vj == vi && sidx[j] < ii);
        }
        ssel[i] = (r < TOPK);
        if (r < TOPK) stop[r] = i;
    }
    __syncthreads();

    const float v32 = sval[stop[TOPK - 1]];

    for (int i = tid; i < n; i += 128) {
        if (fabsf(sval[i] - v32) <= BAND) {
            const int p = atomicAdd(&s_nb, 1);
            if (p < NB_MAX) s_band[p] = i;
            if (ssel[i]) atomicAdd(&s_nsb, 1);
        }
    }
    __syncthreads();
    const int nb = s_nb, nsb = s_nsb;
    if (nb > NB_MAX) { if (tid == 0) g_flag[row] = 1; return; }

    const bool refine = (nb > nsb);
    if (refine) {
        const float* xr = x + (size_t)row * DIN;
        for (int c = 0; c < nb; c++) {
            const float* wr = g_WT + (size_t)sidx[s_band[c]] * DIN;
            double p = 0.0;
            for (int k = tid; k < DIN; k += 128)
                p += (double)xr[k] * (double)wr[k];
            dred[tid] = p;
            __syncthreads();
            for (int s = 64; s > 0; s >>= 1) {
                if (tid < s) dred[tid] += dred[tid + s];
                __syncthreads();
            }
            if (tid == 0) s_exact[c] = dred[0];
            __syncthreads();
        }
    }
    if (tid == 0) {
        int cnt = 0;
        if (refine) {
            for (int r = 0; r < TOPK; r++) {
                const int i = stop[r];
                if (fabsf(sval[i] - v32) > BAND) s_final[cnt++] = i;
            }
            unsigned long long chosen = 0ull;
            for (int t = 0; t < nsb; t++) {
                int best = -1;
                for (int c = 0; c < nb; c++) {
                    if ((chosen >> c) & 1ull) continue;
                    if (best < 0 ||
                        s_exact[c] > s_exact[best] ||
                        (s_exact[c] == s_exact[best] &&
                         sidx[s_band[c]] < sidx[s_band[best]]))
                        best = c;
                }
                chosen |= 1ull << best;
                s_final[cnt++] = s_band[best];
            }
        } else {
            for (int r = 0; r < TOPK; r++) s_final[r] = stop[r];
        }
    }
    __syncthreads();

    // exact fp32 values for the 32 selected
    const int wid = tid >> 5, lane = tid & 31;
    const float* xr = x + (size_t)row * DIN;
    #pragma unroll
    for (int j = 0; j < 8; j++) {
        const int slot = wid * 8 + j;
        const int f = sidx[s_final[slot]];
        const float* wr = g_WT + (size_t)f * DIN;
        float s = 0.f;
        #pragma unroll 8
        for (int k = lane; k < DIN; k += 32)
            s = fmaf(xr[k], wr[k], s);
        #pragma unroll
        for (int o = 16; o > 0; o >>= 1)
            s += __shfl_xor_sync(0xFFFFFFFFu, s, o);
        if (lane == 0) {
            const float v = fmaxf(s + benc[f], 0.f);
            s_fidx[slot] = f;
            s_fval[slot] = v;
            H[(size_t)row * DSAE + f] = v;
            if (v > 0.f) atomicAdd(&s_l0, 1);
        }
    }
    __syncthreads();

    // decode: x_hat = h_sparse @ W_dec + b_dec (8 cols per thread)
    const int c = tid * 8;
    float4 a0 = *(const float4*)(bdec + c);
    float4 a1 = *(const float4*)(bdec + c + 4);
    #pragma unroll 4
    for (int j = 0; j < TOPK; j++) {
        const float v = s_fval[j];
        const float* wr = Wdec + (size_t)s_fidx[j] * DIN + c;
        const float4 w0 = *(const float4*)(wr);
        const float4 w1 = *(const float4*)(wr + 4);
        a0.x += v * w0.x; a0.y += v * w0.y; a0.z += v * w0.z; a0.w += v * w0.w;
        a1.x += v * w1.x; a1.y += v * w1.y; a1.z += v * w1.z; a1.w += v * w1.w;
    }
    const float4 x0 = *(const float4*)(xr + c);
    const float4 x1 = *(const float4*)(xr + c + 4);
    *(float4*)(xhat + (size_t)row * DIN + c) = a0;
    *(float4*)(xhat + (size_t)row * DIN + c + 4) = a1;

    float ls = 0.f;
    ls += (a0.x - x0.x) * (a0.x - x0.x) + (a0.y - x0.y) * (a0.y - x0.y);
    ls += (a0.z - x0.z) * (a0.z - x0.z) + (a0.w - x0.w) * (a0.w - x0.w);
    ls += (a1.x - x1.x) * (a1.x - x1.x) + (a1.y - x1.y) * (a1.y - x1.y);
    ls += (a1.z - x1.z) * (a1.z - x1.z) + (a1.w - x1.w) * (a1.w - x1.w);
    red[tid] = ls;
    __syncthreads();
    for (int s = 64; s > 0; s >>= 1) {
        if (tid < s) red[tid] += red[tid + s];
        __syncthreads();
    }
    if (tid == 0) {
        atomicAdd(&g_loss_sum, (double)red[0]);
        atomicAdd(&g_l0_sum, (float)s_l0);
    }
}

// ---------------- fallback: exact fp64 top-k + decode (flag-driven, ~never runs) ----------------
__global__ __launch_bounds__(256)
void fallback_kernel(const float* __restrict__ x, const float* __restrict__ benc,
                     const float* __restrict__ Wdec, const float* __restrict__ bdec,
                     float* __restrict__ H, float* __restrict__ xhat)
{
    const int row = blockIdx.x;
    if (!g_flag[row]) return;
    const int tid = threadIdx.x;
    __shared__ int s_slot;
    __shared__ double s_bv[256];
    __shared__ int    s_bi[256];
    __shared__ int    s_l0;
    __shared__ int    s_fidx[TOPK];
    __shared__ float  s_fval[TOPK];
    __shared__ float  red[256];
    if (tid == 0) { s_slot = atomicAdd(&g_fbn, 1); s_l0 = 0; }
    __syncthreads();
    const int slot = s_slot;
    double* vrow = (slot < FB_MAX) ? (g_fbv + (size_t)slot * DSAE) : nullptr;
    const float* xr = x + (size_t)row * DIN;

    if (vrow) {
        for (int f = tid; f < DSAE; f += 256) {
            const float* wr = g_WT + (size_t)f * DIN;
            double s = 0.0;
            for (int k = 0; k < DIN; k++) s += (double)xr[k] * (double)wr[k];
            vrow[f] = s + (double)benc[f];
        }
        __syncthreads();
    }

    double pv = 1e300; int pi = -1;
    for (int t = 0; t < TOPK; t++) {
        double bv = -1e300; int bi = -1;
        for (int f = tid; f < DSAE; f += 256) {
            double v;
            if (vrow) v = vrow[f];
            else {
                const float* wr = g_WT + (size_t)f * DIN;
                double s = 0.0;
                for (int k = 0; k < DIN; k++) s += (double)xr[k] * (double)wr[k];
                v = s + (double)benc[f];
            }
            const bool after = (v < pv) || (v == pv && f > pi);
            if (after && (v > bv || (v == bv && f < bi))) { bv = v; bi = f; }
        }
        s_bv[tid] = bv; s_bi[tid] = bi;
        __syncthreads();
        for (int s = 128; s > 0; s >>= 1) {
            if (tid < s) {
                if (s_bv[tid + s] > s_bv[tid] ||
                    (s_bv[tid + s] == s_bv[tid] && s_bi[tid + s] >= 0 &&
                     (s_bi[tid] < 0 || s_bi[tid + s] < s_bi[tid]))) {
                    s_bv[tid] = s_bv[tid + s]; s_bi[tid] = s_bi[tid + s];
                }
            }
            __syncthreads();
        }
        pv = s_bv[0]; pi = s_bi[0];
        __syncthreads();
        if (tid == 0) {
            const float v = fmaxf((float)pv, 0.f);
            s_fidx[t] = pi; s_fval[t] = v;
            H[(size_t)row * DSAE + pi] = v;
            if (v > 0.f) s_l0++;
        }
        __syncthreads();
    }

    // decode for this row
    const int c = tid * 4;
    float4 a0 = *(const float4*)(bdec + c);
    #pragma unroll 4
    for (int j = 0; j < TOPK; j++) {
        const float v = s_fval[j];
        const float4 w = *(const float4*)(Wdec + (size_t)s_fidx[j] * DIN + c);
        a0.x += v * w.x; a0.y += v * w.y; a0.z += v * w.z; a0.w += v * w.w;
    }
    const float4 xv = *(const float4*)(xr + c);
    *(float4*)(xhat + (size_t)row * DIN + c) = a0;
    red[tid] = (a0.x - xv.x) * (a0.x - xv.x) + (a0.y - xv.y) * (a0.y - xv.y)
             + (a0.z - xv.z) * (a0.z - xv.z) + (a0.w - xv.w) * (a0.w - xv.w);
    __syncthreads();
    for (int s = 128; s > 0; s >>= 1) {
        if (tid < s) red[tid] += red[tid + s];
        __syncthreads();
    }
    if (tid == 0) {
        atomicAdd(&g_loss_sum, (double)red[0]);
        atomicAdd(&g_l0_sum, (float)s_l0);
    }
}

__global__ void finalize_kernel(float* __restrict__ out_loss, float* __restrict__ out_l0)
{
    out_loss[0] = (float)(g_loss_sum / ((double)BATCH * (double)DIN));
    out_l0[0]   = g_l0_sum / (float)BATCH;
}

// ---------------- launch ----------------
extern "C" void kernel_launch(void* const* d_in, const int* in_sizes, int n_in,
                              void* d_out, int out_size)
{
    const float* x     = (const float*)d_in[0];
    const float* W_enc = (const float*)d_in[1];
    const float* b_enc = (const float*)d_in[2];
    const float* W_dec = (const float*)d_in[3];
    const float* b_dec = (const float*)d_in[4];

    float* out   = (float*)d_out;
    float* xhat  = out;
    float* H     = out + (size_t)BATCH * DIN;
    float* oloss = out + (size_t)BATCH * DIN + (size_t)BATCH * DSAE;
    float* ol0   = oloss + 1;

    (void)in_sizes; (void)n_in; (void)out_size;

    cudaFuncSetAttribute(gemm_mma_kernel,
                         cudaFuncAttributeMaxDynamicSharedMemorySize, SM_TOTAL);

    init_kernel<<<BATCH / 256, 256>>>();

    splitx_kernel<<<BATCH / 8, 256>>>(x);
    dim3 wb(32, 8);
    splitw_kernel<<<dim3(DSAE / 32, DIN / 32), wb>>>(W_enc);

    dim3 gg(DSAE / 256, BATCH / 128);  // (64, 64)
    gemm_mma_kernel<<<gg, 256, SM_TOTAL>>>(b_enc, H);

    select_decode_kernel<<<BATCH, 128>>>(x, b_enc, W_dec, b_dec, H, xhat);

    fallback_kernel<<<BATCH, 256>>>(x, b_enc, W_dec, b_dec, H, xhat);

    finalize_kernel<<<1, 1>>>(oloss, ol0);
}

// round 8
// speedup vs baseline: 1.2851x; 1.2851x over previous
#include <cuda_runtime.h>
#include <cuda_bf16.h>
#include <cstdint>

#define BATCH 8192
#define DIN   1024
#define DSAE  16384
#define TOPK  32
#define CAP   768
#define NB_MAX 64
#define BAND  2.0e-2f
#define FB_MAX 128

// ---------------- scratch ----------------
__device__ double g_loss_sum;
__device__ float  g_l0_sum;
__device__ float  g_T0[BATCH];
__device__ int    g_cnt[BATCH];
__device__ int    g_flag[BATCH];
__device__ int    g_fbn;
__device__ __align__(16)   uint2 g_cand[(size_t)BATCH * CAP];
__device__ __align__(16)   double g_fbv[(size_t)FB_MAX * DSAE];
__device__ __align__(1024) __nv_bfloat16 g_Xh[BATCH * DIN];
__device__ __align__(1024) __nv_bfloat16 g_Wh[(size_t)DSAE * DIN];
__device__ __align__(1024) float         g_WT[(size_t)DSAE * DIN];

__global__ void init_kernel() {
    const int i = blockIdx.x * blockDim.x + threadIdx.x;
    if (i < BATCH) { g_cnt[i] = 0; g_flag[i] = 0; }
    if (i == 0) { g_loss_sum = 0.0; g_l0_sum = 0.0f; g_fbn = 0; }
}

// ---------------- prep: bf16 x + per-row candidate threshold ----------------
__global__ __launch_bounds__(256)
void splitx_kernel(const float* __restrict__ x)
{
    const int row  = blockIdx.x * 8 + (threadIdx.x >> 5);
    const int lane = threadIdx.x & 31;
    const float* xr = x + (size_t)row * DIN;
    __nv_bfloat16* dr = g_Xh + (size_t)row * DIN;
    float ss = 0.f;
    #pragma unroll
    for (int i = 0; i < 8; i++) {
        const int k = lane * 4 + i * 128;
        const float4 v = *(const float4*)(xr + k);
        ss += v.x * v.x + v.y * v.y + v.z * v.z + v.w * v.w;
        dr[k + 0] = __float2bfloat16_rn(v.x);
        dr[k + 1] = __float2bfloat16_rn(v.y);
        dr[k + 2] = __float2bfloat16_rn(v.z);
        dr[k + 3] = __float2bfloat16_rn(v.w);
    }
    #pragma unroll
    for (int o = 16; o > 0; o >>= 1) ss += __shfl_xor_sync(0xFFFFFFFFu, ss, o);
    if (lane == 0) g_T0[row] = 2.40f * 0.04419417f * sqrtf(ss);
}

// ---------------- prep: transpose W_enc -> fp32 W^T + bf16 W^T ----------------
__global__ __launch_bounds__(256)
void splitw_kernel(const float* __restrict__ W)
{
    __shared__ float t[32][33];
    const int n0 = blockIdx.x * 32, k0 = blockIdx.y * 32;
    const int tx = threadIdx.x, ty = threadIdx.y;  // 32 x 8
    #pragma unroll
    for (int i = 0; i < 32; i += 8)
        t[ty + i][tx] = W[(size_t)(k0 + ty + i) * DSAE + n0 + tx];
    __syncthreads();
    #pragma unroll
    for (int i = 0; i < 32; i += 8) {
        const float v = t[tx][ty + i];
        const size_t o = (size_t)(n0 + ty + i) * DIN + k0 + tx;
        g_Wh[o] = __float2bfloat16_rn(v);
        g_WT[o] = v;
    }
}

// ---------------- helpers ----------------
__device__ __forceinline__ uint32_t smem_u32(const void* p) {
    uint32_t a;
    asm("{ .reg .u64 t; cvta.to.shared.u64 t, %1; cvt.u32.u64 %0, t; }" : "=r"(a) : "l"(p));
    return a;
}
#define SWZ(off) ((off) ^ (((off) >> 3) & 0x70))

__device__ __forceinline__ void ldsm4(uint32_t* r, uint32_t addr) {
    asm volatile("ldmatrix.sync.aligned.m8n8.x4.shared.b16 {%0,%1,%2,%3}, [%4];"
        : "=r"(r[0]), "=r"(r[1]), "=r"(r[2]), "=r"(r[3]) : "r"(addr));
}
__device__ __forceinline__ void mma_bf16(float* d, const uint32_t* a, const uint32_t* b) {
    asm volatile(
        "mma.sync.aligned.m16n8k16.row.col.f32.bf16.bf16.f32 "
        "{%0,%1,%2,%3}, {%4,%5,%6,%7}, {%8,%9}, {%0,%1,%2,%3};"
        : "+f"(d[0]), "+f"(d[1]), "+f"(d[2]), "+f"(d[3])
        : "r"(a[0]), "r"(a[1]), "r"(a[2]), "r"(a[3]), "r"(b[0]), "r"(b[1]));
}

// smem: 2 buffers x 32KB (A 16K | B 16K), then bias 512B, T0 512B
#define SBUF     32768
#define OFF_A    0
#define OFF_B    16384
#define OFF_BIAS 65536
#define OFF_T0   66048
#define SM_TOTAL 66560

// ---------------- encoder GEMM: CTA 128x128, warp tile 32x64, 2-stage, 2 CTA/SM ----------------
__global__ __launch_bounds__(256, 2)
void gemm_mma_kernel(const float* __restrict__ bias, float* __restrict__ H)
{
    extern __shared__ char smem[];
    const uint32_t sb = smem_u32(smem);
    const int tid  = threadIdx.x;
    const int wid  = tid >> 5, lane = tid & 31;
    const int m0   = blockIdx.y * 128;
    const int n0   = blockIdx.x * 128;
    const int m_off = (wid & 3) * 32;
    const int n_off = (wid >> 2) * 64;

    if (tid < 128) {
        *(float*)(smem + OFF_BIAS + tid * 4) = bias[n0 + tid];
        *(float*)(smem + OFF_T0   + tid * 4) = g_T0[m0 + tid];
    }

    float acc[2][8][4] = {};

#define ISSUE_STAGE(s) do {                                                          \
    const int k0_ = (s) * 64;                                                        \
    const uint32_t base_ = sb + ((s) & 1) * SBUF;                                    \
    _Pragma("unroll")                                                                \
    for (int i = 0; i < 4; i++) {                                                    \
        const int c = tid + i * 256;                                                 \
        const int row = c >> 3, c16 = c & 7;                                         \
        const uint32_t off = SWZ((uint32_t)(row * 128 + c16 * 16));                  \
        const size_t gA = (size_t)(m0 + row) * DIN + k0_ + c16 * 8;                  \
        const size_t gB = (size_t)(n0 + row) * DIN + k0_ + c16 * 8;                  \
        asm volatile("cp.async.cg.shared.global [%0], [%1], 16;"                     \
                     :: "r"(base_ + OFF_A + off), "l"(g_Xh + gA) : "memory");        \
        asm volatile("cp.async.cg.shared.global [%0], [%1], 16;"                     \
                     :: "r"(base_ + OFF_B + off), "l"(g_Wh + gB) : "memory");        \
    }                                                                                \
    asm volatile("cp.async.commit_group;" ::: "memory");                             \
} while (0)

    ISSUE_STAGE(0);

    const int NST = DIN / 64;  // 16
    for (int s = 0; s < NST; s++) {
        if (s + 1 < NST) {
            ISSUE_STAGE(s + 1);
            asm volatile("cp.async.wait_group 1;" ::: "memory");
        } else {
            asm volatile("cp.async.wait_group 0;" ::: "memory");
        }
        __syncthreads();

        const uint32_t base = sb + (s & 1) * SBUF;
        #pragma unroll
        for (int ks = 0; ks < 4; ks++) {
            const int kb = ks * 16;
            uint32_t ah[2][4];
            #pragma unroll
            for (int fm = 0; fm < 2; fm++) {
                const int row = m_off + fm * 16 + (lane & 15);
                const int col = kb + (lane >> 4) * 8;
                const uint32_t off = SWZ((uint32_t)(row * 128 + col * 2));
                ldsm4(ah[fm], base + OFF_A + off);
            }
            uint32_t bh[8][2];
            #pragma unroll
            for (int p = 0; p < 4; p++) {
                const int nrow = n_off + p * 16 + (lane & 7) + ((lane >> 4) & 1) * 8;
                const int kcol = kb + ((lane >> 3) & 1) * 8;
                const uint32_t off = SWZ((uint32_t)(nrow * 128 + kcol * 2));
                uint32_t t[4];
                ldsm4(t, base + OFF_B + off);
                bh[2 * p][0] = t[0]; bh[2 * p][1] = t[1];
                bh[2 * p + 1][0] = t[2]; bh[2 * p + 1][1] = t[3];
            }
            #pragma unroll
            for (int fm = 0; fm < 2; fm++)
                #pragma unroll
                for (int fn = 0; fn < 8; fn++)
                    mma_bf16(acc[fm][fn], ah[fm], bh[fn]);
        }
        __syncthreads();
    }
#undef ISSUE_STAGE

    // epilogue: zero-fill h_sparse tile; candidates (v > T0[row]) -> global list
    const float* bs = (const float*)(smem + OFF_BIAS);
    const float* t0 = (const float*)(smem + OFF_T0);
    #pragma unroll
    for (int fm = 0; fm < 2; fm++) {
        #pragma unroll
        for (int fn = 0; fn < 8; fn++) {
            const int nc = n_off + fn * 8 + (lane & 3) * 2;
            const float b0 = bs[nc], b1 = bs[nc + 1];
            #pragma unroll
            for (int half = 0; half < 2; half++) {
                const int lr = m_off + fm * 16 + (lane >> 2) + half * 8;
                const int m = m0 + lr;
                const float v0 = acc[fm][fn][half * 2 + 0] + b0;
                const float v1 = acc[fm][fn][half * 2 + 1] + b1;
                *(float2*)(H + (size_t)m * DSAE + n0 + nc) = make_float2(0.f, 0.f);
                const float th = t0[lr];
                if (v0 > th) {
                    const int p = atomicAdd(&g_cnt[m], 1);
                    if (p < CAP) g_cand[(size_t)m * CAP + p] =
                        make_uint2(__float_as_uint(v0), (unsigned)(n0 + nc));
                }
                if (v1 > th) {
                    const int p = atomicAdd(&g_cnt[m], 1);
                    if (p < CAP) g_cand[(size_t)m * CAP + p] =
                        make_uint2(__float_as_uint(v1), (unsigned)(n0 + nc + 1));
                }
            }
        }
    }
}

// ---------------- fused select + valuefix + decode + loss (per row) ----------------
__global__ __launch_bounds__(128)
void select_decode_kernel(const float* __restrict__ x, const float* __restrict__ benc,
                          const float* __restrict__ Wdec, const float* __restrict__ bdec,
                          float* __restrict__ H, float* __restrict__ xhat)
{
    __shared__ float sval[CAP];
    __shared__ int   sidx[CAP];
    __shared__ unsigned char ssel[CAP];
    __shared__ int   stop[TOPK];
    __shared__ int   s_band[NB_MAX];
    __shared__ double s_exact[NB_MAX];
    __shared__ double dred[128];
    __shared__ int   s_nb, s_nsb, s_l0;
    __shared__ int   s_final[TOPK];
    __shared__ int   s_fidx[TOPK];
    __shared__ float s_fval[TOPK];
    __shared__ float red[128];

    const int row = blockIdx.x;
    const int tid = threadIdx.x;
    const int n = g_cnt[row];
    if (n < TOPK || n > CAP) { if (tid == 0) g_flag[row] = 1; return; }

    for (int i = tid; i < n; i += 128) {
        const uint2 c = g_cand[(size_t)row * CAP + i];
        sval[i] = __uint_as_float(c.x);
        sidx[i] = (int)c.y;
    }
    if (tid == 0) { s_nb = 0; s_nsb = 0; s_l0 = 0; }
    __syncthreads();

    // exact rank by (value desc, idx asc)
    for (int i = tid; i < n; i += 128) {
        const float vi = sval[i]; const int ii = sidx[i];
        int r = 0;
        for (int j = 0; j < n; j++) {
            const float vj = sval[j];
            r += (vj > vi) || (vj == vi && sidx[j] < ii);
        }
        ssel[i] = (r < TOPK);
        if (r < TOPK) stop[r] = i;
    }
    __syncthreads();

    const float v32 = sval[stop[TOPK - 1]];

    for (int i = tid; i < n; i += 128) {
        if (fabsf(sval[i] - v32) <= BAND) {
            const int p = atomicAdd(&s_nb, 1);
            if (p < NB_MAX) s_band[p] = i;
            if (ssel[i]) atomicAdd(&s_nsb, 1);
        }
    }
    __syncthreads();
    const int nb = s_nb, nsb = s_nsb;
    if (nb > NB_MAX) { if (tid == 0) g_flag[row] = 1; return; }

    const bool refine = (nb > nsb);
    if (refine) {
        const float* xr = x + (size_t)row * DIN;
        for (int c = 0; c < nb; c++) {
            const float* wr = g_WT + (size_t)sidx[s_band[c]] * DIN;
            double p = 0.0;
            for (int k = tid; k < DIN; k += 128)
                p += (double)xr[k] * (double)wr[k];
            dred[tid] = p;
            __syncthreads();
            for (int s = 64; s > 0; s >>= 1) {
                if (tid < s) dred[tid] += dred[tid + s];
                __syncthreads();
            }
            if (tid == 0) s_exact[c] = dred[0];
            __syncthreads();
        }
    }
    if (tid == 0) {
        int cnt = 0;
        if (refine) {
            for (int r = 0; r < TOPK; r++) {
                const int i = stop[r];
                if (fabsf(sval[i] - v32) > BAND) s_final[cnt++] = i;
            }
            unsigned long long chosen = 0ull;
            for (int t = 0; t < nsb; t++) {
                int best = -1;
                for (int c = 0; c < nb; c++) {
                    if ((chosen >> c) & 1ull) continue;
                    if (best < 0 ||
                        s_exact[c] > s_exact[best] ||
                        (s_exact[c] == s_exact[best] &&
                         sidx[s_band[c]] < sidx[s_band[best]]))
                        best = c;
                }
                chosen |= 1ull << best;
                s_final[cnt++] = s_band[best];
            }
        } else {
            for (int r = 0; r < TOPK; r++) s_final[r] = stop[r];
        }
    }
    __syncthreads();

    // exact fp32 values for the 32 selected
    const int wid = tid >> 5, lane = tid & 31;
    const float* xr = x + (size_t)row * DIN;
    #pragma unroll
    for (int j = 0; j < 8; j++) {
        const int slot = wid * 8 + j;
        const int f = sidx[s_final[slot]];
        const float* wr = g_WT + (size_t)f * DIN;
        float s = 0.f;
        #pragma unroll 8
        for (int k = lane; k < DIN; k += 32)
            s = fmaf(xr[k], wr[k], s);
        #pragma unroll
        for (int o = 16; o > 0; o >>= 1)
            s += __shfl_xor_sync(0xFFFFFFFFu, s, o);
        if (lane == 0) {
            const float v = fmaxf(s + benc[f], 0.f);
            s_fidx[slot] = f;
            s_fval[slot] = v;
            H[(size_t)row * DSAE + f] = v;
            if (v > 0.f) atomicAdd(&s_l0, 1);
        }
    }
    __syncthreads();

    // decode: x_hat = h_sparse @ W_dec + b_dec (8 cols per thread)
    const int c = tid * 8;
    float4 a0 = *(const float4*)(bdec + c);
    float4 a1 = *(const float4*)(bdec + c + 4);
    #pragma unroll 4
    for (int j = 0; j < TOPK; j++) {
        const float v = s_fval[j];
        const float* wr = Wdec + (size_t)s_fidx[j] * DIN + c;
        const float4 w0 = *(const float4*)(wr);
        const float4 w1 = *(const float4*)(wr + 4);
        a0.x += v * w0.x; a0.y += v * w0.y; a0.z += v * w0.z; a0.w += v * w0.w;
        a1.x += v * w1.x; a1.y += v * w1.y; a1.z += v * w1.z; a1.w += v * w1.w;
    }
    const float4 x0 = *(const float4*)(xr + c);
    const float4 x1 = *(const float4*)(xr + c + 4);
    *(float4*)(xhat + (size_t)row * DIN + c) = a0;
    *(float4*)(xhat + (size_t)row * DIN + c + 4) = a1;

    float ls = 0.f;
    ls += (a0.x - x0.x) * (a0.x - x0.x) + (a0.y - x0.y) * (a0.y - x0.y);
    ls += (a0.z - x0.z) * (a0.z - x0.z) + (a0.w - x0.w) * (a0.w - x0.w);
    ls += (a1.x - x1.x) * (a1.x - x1.x) + (a1.y - x1.y) * (a1.y - x1.y);
    ls += (a1.z - x1.z) * (a1.z - x1.z) + (a1.w - x1.w) * (a1.w - x1.w);
    red[tid] = ls;
    __syncthreads();
    for (int s = 64; s > 0; s >>= 1) {
        if (tid < s) red[tid] += red[tid + s];
        __syncthreads();
    }
    if (tid == 0) {
        atomicAdd(&g_loss_sum, (double)red[0]);
        atomicAdd(&g_l0_sum, (float)s_l0);
    }
}

// ---------------- fallback: exact fp64 top-k + decode (flag-driven, ~never runs) ----------------
__global__ __launch_bounds__(256)
void fallback_kernel(const float* __restrict__ x, const float* __restrict__ benc,
                     const float* __restrict__ Wdec, const float* __restrict__ bdec,
                     float* __restrict__ H, float* __restrict__ xhat)
{
    const int row = blockIdx.x;
    if (!g_flag[row]) return;
    const int tid = threadIdx.x;
    __shared__ int s_slot;
    __shared__ double s_bv[256];
    __shared__ int    s_bi[256];
    __shared__ int    s_l0;
    __shared__ int    s_fidx[TOPK];
    __shared__ float  s_fval[TOPK];
    __shared__ float  red[256];
    if (tid == 0) { s_slot = atomicAdd(&g_fbn, 1); s_l0 = 0; }
    __syncthreads();
    const int slot = s_slot;
    double* vrow = (slot < FB_MAX) ? (g_fbv + (size_t)slot * DSAE) : nullptr;
    const float* xr = x + (size_t)row * DIN;

    if (vrow) {
        for (int f = tid; f < DSAE; f += 256) {
            const float* wr = g_WT + (size_t)f * DIN;
            double s = 0.0;
            for (int k = 0; k < DIN; k++) s += (double)xr[k] * (double)wr[k];
            vrow[f] = s + (double)benc[f];
        }
        __syncthreads();
    }

    double pv = 1e300; int pi = -1;
    for (int t = 0; t < TOPK; t++) {
        double bv = -1e300; int bi = -1;
        for (int f = tid; f < DSAE; f += 256) {
            double v;
            if (vrow) v = vrow[f];
            else {
                const float* wr = g_WT + (size_t)f * DIN;
                double s = 0.0;
                for (int k = 0; k < DIN; k++) s += (double)xr[k] * (double)wr[k];
                v = s + (double)benc[f];
            }
            const bool after = (v < pv) || (v == pv && f > pi);
            if (after && (v > bv || (v == bv && f < bi))) { bv = v; bi = f; }
        }
        s_bv[tid] = bv; s_bi[tid] = bi;
        __syncthreads();
        for (int s = 128; s > 0; s >>= 1) {
            if (tid < s) {
                if (s_bv[tid + s] > s_bv[tid] ||
                    (s_bv[tid + s] == s_bv[tid] && s_bi[tid + s] >= 0 &&
                     (s_bi[tid] < 0 || s_bi[tid + s] < s_bi[tid]))) {
                    s_bv[tid] = s_bv[tid + s]; s_bi[tid] = s_bi[tid + s];
                }
            }
            __syncthreads();
        }
        pv = s_bv[0]; pi = s_bi[0];
        __syncthreads();
        if (tid == 0) {
            const float v = fmaxf((float)pv, 0.f);
            s_fidx[t] = pi; s_fval[t] = v;
            H[(size_t)row * DSAE + pi] = v;
            if (v > 0.f) s_l0++;
        }
        __syncthreads();
    }

    // decode for this row
    const int c = tid * 4;
    float4 a0 = *(const float4*)(bdec + c);
    #pragma unroll 4
    for (int j = 0; j < TOPK; j++) {
        const float v = s_fval[j];
        const float4 w = *(const float4*)(Wdec + (size_t)s_fidx[j] * DIN + c);
        a0.x += v * w.x; a0.y += v * w.y; a0.z += v * w.z; a0.w += v * w.w;
    }
    const float4 xv = *(const float4*)(xr + c);
    *(float4*)(xhat + (size_t)row * DIN + c) = a0;
    red[tid] = (a0.x - xv.x) * (a0.x - xv.x) + (a0.y - xv.y) * (a0.y - xv.y)
             + (a0.z - xv.z) * (a0.z - xv.z) + (a0.w - xv.w) * (a0.w - xv.w);
    __syncthreads();
    for (int s = 128; s > 0; s >>= 1) {
        if (tid < s) red[tid] += red[tid + s];
        __syncthreads();
    }
    if (tid == 0) {
        atomicAdd(&g_loss_sum, (double)red[0]);
        atomicAdd(&g_l0_sum, (float)s_l0);
    }
}

__global__ void finalize_kernel(float* __restrict__ out_loss, float* __restrict__ out_l0)
{
    out_loss[0] = (float)(g_loss_sum / ((double)BATCH * (double)DIN));
    out_l0[0]   = g_l0_sum / (float)BATCH;
}

// ---------------- launch ----------------
extern "C" void kernel_launch(void* const* d_in, const int* in_sizes, int n_in,
                              void* d_out, int out_size)
{
    const float* x     = (const float*)d_in[0];
    const float* W_enc = (const float*)d_in[1];
    const float* b_enc = (const float*)d_in[2];
    const float* W_dec = (const float*)d_in[3];
    const float* b_dec = (const float*)d_in[4];

    float* out   = (float*)d_out;
    float* xhat  = out;
    float* H     = out + (size_t)BATCH * DIN;
    float* oloss = out + (size_t)BATCH * DIN + (size_t)BATCH * DSAE;
    float* ol0   = oloss + 1;

    (void)in_sizes; (void)n_in; (void)out_size;

    cudaFuncSetAttribute(gemm_mma_kernel,
                         cudaFuncAttributeMaxDynamicSharedMemorySize, SM_TOTAL);

    init_kernel<<<BATCH / 256, 256>>>();

    splitx_kernel<<<BATCH / 8, 256>>>(x);
    dim3 wb(32, 8);
    splitw_kernel<<<dim3(DSAE / 32, DIN / 32), wb>>>(W_enc);

    dim3 gg(DSAE / 128, BATCH / 128);  // (128, 64)
    gemm_mma_kernel<<<gg, 256, SM_TOTAL>>>(b_enc, H);

    select_decode_kernel<<<BATCH, 128>>>(x, b_enc, W_dec, b_dec, H, xhat);

    fallback_kernel<<<BATCH, 256>>>(x, b_enc, W_dec, b_dec, H, xhat);

    finalize_kernel<<<1, 1>>>(oloss, ol0);
}